// round 11
// baseline (speedup 1.0000x reference)
#include <cuda_runtime.h>
#include <cuda_bf16.h>
#include <cstdint>

// Problem constants (fixed shapes)
#define DD   256   // feature dim
#define KK   256   // num centers
#define OUTD 128   // output dim

// ---------------- constant precompute scratch (device globals) ----------------
__device__ __align__(16) float          g_s[DD];     // relu(sigma)
__device__ __align__(16) float          g_SV[OUTD];  // sum_k V[k,o]
__device__ __align__(16) float          g_Bp[OUTD];  // relu(W0)+sum relu(Wk) - sum c2*V
// Packed B' fragments (e4m3, s pre-folded), mma m16n8k32 layout:
// uint4 idx = (k32*8 + j)*32 + lane; u32 within = (nt&1)*2 + i (i: b0/b1)
__device__ __align__(16) unsigned char  g_Bpk[8 * 8 * 32 * 16];   // 32KB

// ---------------- packed-B writer (fp8) ----------------
__device__ __forceinline__ void write_Bpk(int o, int d, float val) {
    int nt = o >> 3, q = o & 7;
    int k32 = d >> 5, r = d & 31;
    int i  = (r >> 4) & 1;      // b0 (k0-15) / b1 (k16-31)
    int ql = (r & 15) >> 2;     // thread-in-quad
    int h  = r & 3;             // byte within u32
    int lane = q * 4 + ql;
    int u32idx = ((k32 * 8 + (nt >> 1)) * 32 + lane) * 4 + (nt & 1) * 2 + i;
    uint16_t v16;
    asm("cvt.rn.satfinite.e4m3x2.f32 %0, %1, %2;" : "=h"(v16) : "f"(0.0f), "f"(val));
    g_Bpk[u32idx * 4 + h] = (unsigned char)(v16 & 0xFF);
}

// ---------------- fused prep: SV, Bp, packed s-folded M2 — 2 cols per block ----
__global__ void prep_kernel(const float* __restrict__ sigma,
                            const float* __restrict__ center,
                            const float* __restrict__ width,
                            const float* __restrict__ wout) {
    const int o0 = blockIdx.x * 2;
    const int o1 = o0 + 1;
    const int t = threadIdx.x;       // k index for reductions, d index for M2/CV
    __shared__ float V0[KK], V1[KK];
    __shared__ float red[6][8];

    const float s = fmaxf(sigma[t], 0.0f);
    if (blockIdx.x == 0) g_s[t] = s;

    float wk = fmaxf(width[t], 0.0f);
    float w0 = fmaxf(wout[(1 + t) * OUTD + o0], 0.0f);
    float w1 = fmaxf(wout[(1 + t) * OUTD + o1], 0.0f);
    float v0 = wk * w0, v1 = wk * w1;
    V0[t] = v0; V1[t] = v1;

    float r0 = v0, r1 = w0, r3 = v1, r4 = w1;
    #pragma unroll
    for (int off = 16; off; off >>= 1) {
        r0 += __shfl_xor_sync(0xffffffffu, r0, off);
        r1 += __shfl_xor_sync(0xffffffffu, r1, off);
        r3 += __shfl_xor_sync(0xffffffffu, r3, off);
        r4 += __shfl_xor_sync(0xffffffffu, r4, off);
    }
    const int warp = t >> 5, lane = t & 31;
    if (lane == 0) {
        red[0][warp] = r0; red[1][warp] = r1;
        red[3][warp] = r3; red[4][warp] = r4;
    }
    __syncthreads();   // V0/V1 ready

    // M2'[d=t][o] = s_t * 2 * sum_k c[k][t]*V[k][o]  (s folded into B)
    // CV partial:   s_t * sum_k c[k][t]^2 * V[k][o]
    float m0a = 0, m0b = 0, m1a = 0, m1b = 0;
    float q0a = 0, q0b = 0, q1a = 0, q1b = 0;
    #pragma unroll 8
    for (int k = 0; k < KK; k += 2) {
        float ca = center[k * DD + t];
        float cb = center[(k + 1) * DD + t];
        float csa = ca * ca, csb = cb * cb;
        m0a = fmaf(ca, V0[k], m0a);      m0b = fmaf(cb, V0[k + 1], m0b);
        m1a = fmaf(ca, V1[k], m1a);      m1b = fmaf(cb, V1[k + 1], m1b);
        q0a = fmaf(csa, V0[k], q0a);     q0b = fmaf(csb, V0[k + 1], q0b);
        q1a = fmaf(csa, V1[k], q1a);     q1b = fmaf(csb, V1[k + 1], q1b);
    }
    write_Bpk(o0, t, 2.0f * s * (m0a + m0b));
    write_Bpk(o1, t, 2.0f * s * (m1a + m1b));

    float q0 = s * (q0a + q0b), q1 = s * (q1a + q1b);
    #pragma unroll
    for (int off = 16; off; off >>= 1) {
        q0 += __shfl_xor_sync(0xffffffffu, q0, off);
        q1 += __shfl_xor_sync(0xffffffffu, q1, off);
    }
    if (lane == 0) { red[2][warp] = q0; red[5][warp] = q1; }
    __syncthreads();

    if (t < 2) {
        const int o = (t == 0) ? o0 : o1;
        const float* a = red[3 * t];
        const float* b = red[3 * t + 1];
        const float* c = red[3 * t + 2];
        float sv = 0, sw = 0, cv = 0;
        #pragma unroll
        for (int w = 0; w < 8; w++) { sv += a[w]; sw += b[w]; cv += c[w]; }
        g_SV[o] = sv;
        g_Bp[o] = fmaxf(wout[o], 0.0f) + sw - cv;
    }
}

// ---------------- helpers ----------------
__device__ __forceinline__ uint32_t pack_e4m3x4(float f0, float f1, float f2, float f3) {
    uint16_t lo, hi;
    asm("cvt.rn.satfinite.e4m3x2.f32 %0, %1, %2;" : "=h"(lo) : "f"(f1), "f"(f0));
    asm("cvt.rn.satfinite.e4m3x2.f32 %0, %1, %2;" : "=h"(hi) : "f"(f3), "f"(f2));
    return (uint32_t)lo | ((uint32_t)hi << 16);
}

__device__ __forceinline__ void mma_fp8(float* c, uint32_t a0, uint32_t a1,
                                        uint32_t a2, uint32_t a3,
                                        uint32_t b0, uint32_t b1) {
    asm volatile(
        "mma.sync.aligned.m16n8k32.row.col.f32.e4m3.e4m3.f32 "
        "{%0,%1,%2,%3}, {%4,%5,%6,%7}, {%8,%9}, {%0,%1,%2,%3};"
        : "+f"(c[0]), "+f"(c[1]), "+f"(c[2]), "+f"(c[3])
        : "r"(a0), "r"(a1), "r"(a2), "r"(a3), "r"(b0), "r"(b1));
}

__device__ __forceinline__ void ldsm_x4(uint32_t& r0, uint32_t& r1,
                                        uint32_t& r2, uint32_t& r3, uint32_t addr) {
    asm volatile("ldmatrix.sync.aligned.m8n8.x4.shared.b16 {%0,%1,%2,%3}, [%4];"
        : "=r"(r0), "=r"(r1), "=r"(r2), "=r"(r3) : "r"(addr));
}

// ---------------- main kernel: out = Bp - x2*SV + x @ M2' (fp8 GEMM) ----------
// 256 threads = 8 warps, 2(m) x 4(n), warp tile 32x32 (acc = 32 regs).
// Block tile 64 rows x 128 cols. 8 chunks of k32; A tile e4m3, 48B-padded rows
// (conflict-free ldsm/STS, no swizzle), double-buffered, 1 sync per chunk.
__global__ void __launch_bounds__(256, 4)
rbf_main_kernel(const float* __restrict__ x, float* __restrict__ out) {
    __shared__ __align__(16) char smU[64 * 68 * 4];   // A: 2x3KB | fbuf 17.4KB
    __shared__ float x2_sh[64];

    const int tid  = threadIdx.x;
    const int warp = tid >> 5;
    const int lane = tid & 31;
    const int warp_m = warp >> 2;     // 0..1
    const int warp_n = warp & 3;      // 0..3
    const int q8    = lane >> 2;      // 0..7
    const int ql    = lane & 3;       // 0..3

    const int row0 = blockIdx.x * 64;
    const int sr0  = (tid >> 3) * 2;  // staging rows {sr0, sr0+1}
    const int seg  = tid & 7;         // 4-float segment within 32-col chunk

    const uint32_t abase = (uint32_t)__cvta_generic_to_shared(smU);
    const uint4* Bb = reinterpret_cast<const uint4*>(g_Bpk) + warp_n * 64 + lane;

    // STS: st.shared.b32 at row*48 + seg*4  (1 phase per row-subset, verified)
    const uint32_t sts0 = abase + (uint32_t)(sr0 * 48 + seg * 4);
    // ldsm: addr = row*48 + (lane>>4)*16, row = warp_m*32 + mt*16 + (lane&15)
    const uint32_t lds0 = abase + (uint32_t)((warp_m * 32 + (lane & 15)) * 48
                                             + (lane >> 4) * 16);

    float acc[2][4][4];
    #pragma unroll
    for (int mt = 0; mt < 2; mt++)
        #pragma unroll
        for (int nt = 0; nt < 4; nt++)
            #pragma unroll
            for (int i = 0; i < 4; i++) acc[mt][nt][i] = 0.0f;

    float x2p0 = 0.0f, x2p1 = 0.0f;

    const float* xptr = x + (size_t)(row0 + sr0) * DD + seg * 4;
    float4 v0 = __ldcs(reinterpret_cast<const float4*>(xptr));
    float4 v1 = __ldcs(reinterpret_cast<const float4*>(xptr + DD));

    #pragma unroll
    for (int c = 0; c < 8; c++) {
        const float4 sv4 = *reinterpret_cast<const float4*>(g_s + c * 32 + seg * 4);
        const uint32_t boff = (uint32_t)((c & 1) * 3072);

        // x2 (fp32 exact) + fp8 pack + STS (2 rows, 4B each)
        {
            float t0 = v0.x * sv4.x, t1 = v0.y * sv4.y, t2 = v0.z * sv4.z, t3 = v0.w * sv4.w;
            x2p0 += t0 * v0.x + t1 * v0.y + t2 * v0.z + t3 * v0.w;
            uint32_t pk = pack_e4m3x4(v0.x, v0.y, v0.z, v0.w);
            asm volatile("st.shared.b32 [%0], %1;"
                         :: "r"(sts0 + boff), "r"(pk) : "memory");
        }
        {
            float t0 = v1.x * sv4.x, t1 = v1.y * sv4.y, t2 = v1.z * sv4.z, t3 = v1.w * sv4.w;
            x2p1 += t0 * v1.x + t1 * v1.y + t2 * v1.z + t3 * v1.w;
            uint32_t pk = pack_e4m3x4(v1.x, v1.y, v1.z, v1.w);
            asm volatile("st.shared.b32 [%0], %1;"
                         :: "r"(sts0 + 48u + boff), "r"(pk) : "memory");
        }

        // prefetch next chunk's x
        if (c < 7) {
            const float* nb = xptr + (c + 1) * 32;
            v0 = __ldcs(reinterpret_cast<const float4*>(nb));
            v1 = __ldcs(reinterpret_cast<const float4*>(nb + DD));
        }

        // B' fragments for this k32 (global constant — issue before barrier)
        const uint4 bu0 = Bb[c * 256];
        const uint4 bu1 = Bb[c * 256 + 32];

        __syncthreads();   // A[c&1] ready; orders MMA(c-1) before STS(c+1)

        #pragma unroll
        for (int mt = 0; mt < 2; mt++) {
            uint32_t a0, a1, a2, a3;
            ldsm_x4(a0, a1, a2, a3, lds0 + boff + (uint32_t)(mt * 16 * 48));
            mma_fp8(acc[mt][0], a0, a1, a2, a3, bu0.x, bu0.y);
            mma_fp8(acc[mt][1], a0, a1, a2, a3, bu0.z, bu0.w);
            mma_fp8(acc[mt][2], a0, a1, a2, a3, bu1.x, bu1.y);
            mma_fp8(acc[mt][3], a0, a1, a2, a3, bu1.z, bu1.w);
        }
        // no trailing sync: buffers alternate; next sync provides ordering
    }

    // ---- finalize x2: reduce across the 8 lanes sharing each row ----
    x2p0 += __shfl_xor_sync(0xffffffffu, x2p0, 1);
    x2p0 += __shfl_xor_sync(0xffffffffu, x2p0, 2);
    x2p0 += __shfl_xor_sync(0xffffffffu, x2p0, 4);
    x2p1 += __shfl_xor_sync(0xffffffffu, x2p1, 1);
    x2p1 += __shfl_xor_sync(0xffffffffu, x2p1, 2);
    x2p1 += __shfl_xor_sync(0xffffffffu, x2p1, 4);
    if (seg == 0) {
        x2_sh[sr0] = x2p0;
        x2_sh[sr0 + 1] = x2p1;
    }
    __syncthreads();   // x2 ready; all MMAs done -> smU reusable as fbuf

    // ---- epilogue: 2 passes x 64 cols; restage -> coalesced STG.128 ----
    float* fb = reinterpret_cast<float*>(smU);   // 64 rows x 68 floats
    const int rr2 = tid >> 4;      // 0..15
    const int f4  = tid & 15;      // 0..15 float4 col within 64

    #pragma unroll 1
    for (int cc = 0; cc < 2; cc++) {
        if ((warp_n >> 1) == cc) {
            #pragma unroll
            for (int ntl = 0; ntl < 4; ntl++) {
                const int lcol = (warp_n & 1) * 32 + ntl * 8 + 2 * ql;
                #pragma unroll
                for (int mt = 0; mt < 2; mt++) {
                    const int r0 = warp_m * 32 + mt * 16 + q8;
                    *reinterpret_cast<float2*>(fb + r0 * 68 + lcol) =
                        make_float2(acc[mt][ntl][0], acc[mt][ntl][1]);
                    *reinterpret_cast<float2*>(fb + (r0 + 8) * 68 + lcol) =
                        make_float2(acc[mt][ntl][2], acc[mt][ntl][3]);
                }
            }
        }
        __syncthreads();

        const int col0 = cc * 64 + f4 * 4;
        const float4 bp  = *reinterpret_cast<const float4*>(g_Bp + col0);
        const float4 svv = *reinterpret_cast<const float4*>(g_SV + col0);
        #pragma unroll
        for (int i = 0; i < 4; i++) {
            const int row = rr2 + i * 16;
            const float4 u = *reinterpret_cast<const float4*>(fb + row * 68 + f4 * 4);
            const float x2v = x2_sh[row];
            float4 o;
            o.x = u.x + bp.x - x2v * svv.x;
            o.y = u.y + bp.y - x2v * svv.y;
            o.z = u.z + bp.z - x2v * svv.z;
            o.w = u.w + bp.w - x2v * svv.w;
            __stcs(reinterpret_cast<float4*>(out + (size_t)(row0 + row) * OUTD + col0), o);
        }
        __syncthreads();
    }
}

// ---------------- launcher ----------------
extern "C" void kernel_launch(void* const* d_in, const int* in_sizes, int n_in,
                              void* d_out, int out_size) {
    const float* x      = (const float*)d_in[0];  // [N, D]
    const float* center = (const float*)d_in[1];  // [K, D]
    const float* sigma  = (const float*)d_in[2];  // [D]
    const float* width  = (const float*)d_in[3];  // [K]
    const float* wout   = (const float*)d_in[4];  // [1+K, OUT]
    float* out = (float*)d_out;

    const int N = in_sizes[0] / DD;

    prep_kernel<<<OUTD / 2, 256>>>(sigma, center, width, wout);
    rbf_main_kernel<<<N / 64, 256>>>(x, out);
}

// round 13
// speedup vs baseline: 1.2848x; 1.2848x over previous
#include <cuda_runtime.h>
#include <cuda_bf16.h>
#include <cstdint>

// Problem constants (fixed shapes)
#define DD   256   // feature dim
#define KK   256   // num centers
#define OUTD 128   // output dim

#define NPREP 64   // prep blocks: 2 output cols each -> covers OUTD=128 exactly

// ---------------- constant precompute scratch (device globals) ----------------
__device__ __align__(16) float          g_s[DD];     // relu(sigma)
__device__ __align__(16) float          g_SV[OUTD];  // sum_k V[k,o]
__device__ __align__(16) float          g_Bp[OUTD];  // relu(W0)+sum relu(Wk) - sum c2*V
// Packed B' fragments (bf16), s pre-folded: uint4 idx = (k16*8 + j)*32 + lane
__device__ __align__(16) __nv_bfloat16  g_Bpk[16 * 8 * 32 * 4 * 2];   // 64KB

// cross-block handshake (self-resetting each launch)
__device__ int g_ready = 0;   // prep blocks completed
__device__ int g_done  = 0;   // main blocks completed

// ---------------- packed-B writer ----------------
__device__ __forceinline__ void write_Bpk(int o, int d, float val) {
    int nt = o >> 3, q = o & 7;
    int k16 = d >> 4, r = d & 15;
    int i = r >> 3, l = (r & 7) >> 1, h = r & 1;
    int lane = q * 4 + l;
    int u32idx = ((k16 * 8 + (nt >> 1)) * 32 + lane) * 4 + (nt & 1) * 2 + i;
    g_Bpk[u32idx * 2 + h] = __float2bfloat16(val);
}

// ---------------- helpers ----------------
__device__ __forceinline__ uint32_t pack_bf16x2(float lo, float hi) {
    uint32_t r;
    asm("cvt.rn.bf16x2.f32 %0, %1, %2;" : "=r"(r) : "f"(hi), "f"(lo));
    return r;
}

__device__ __forceinline__ void mma16816(float* c, uint32_t a0, uint32_t a1,
                                         uint32_t a2, uint32_t a3,
                                         uint32_t b0, uint32_t b1) {
    asm volatile(
        "mma.sync.aligned.m16n8k16.row.col.f32.bf16.bf16.f32 "
        "{%0,%1,%2,%3}, {%4,%5,%6,%7}, {%8,%9}, {%0,%1,%2,%3};"
        : "+f"(c[0]), "+f"(c[1]), "+f"(c[2]), "+f"(c[3])
        : "r"(a0), "r"(a1), "r"(a2), "r"(a3), "r"(b0), "r"(b1));
}

__device__ __forceinline__ void ldsm_x4(uint32_t& r0, uint32_t& r1,
                                        uint32_t& r2, uint32_t& r3, uint32_t addr) {
    asm volatile("ldmatrix.sync.aligned.m8n8.x4.shared.b16 {%0,%1,%2,%3}, [%4];"
        : "=r"(r0), "=r"(r1), "=r"(r2), "=r"(r3) : "r"(addr));
}

// ---------------- fused kernel: blocks [0,64) prep, [64, 64+N/64) main -------
__global__ void __launch_bounds__(256, 4)
rbf_fused_kernel(const float* __restrict__ x,
                 const float* __restrict__ center,
                 const float* __restrict__ sigma,
                 const float* __restrict__ width,
                 const float* __restrict__ wout,
                 float* __restrict__ out, int n_main) {
    __shared__ __align__(16) char smU[64 * 68 * 4];
    __shared__ float x2_sh[64];

    const int tid = threadIdx.x;

    if (blockIdx.x < NPREP) {
        // =================== PREP: SV, Bp, packed s-folded M2 ===================
        float* V0 = reinterpret_cast<float*>(smU);            // [KK]
        float* V1 = V0 + KK;                                  // [KK]
        float* red = V1 + KK;                                 // [6][8]

        const int o0 = blockIdx.x * 2;        // 0..126 — in range (NPREP=64)
        const int o1 = o0 + 1;
        const int t = tid;

        const float s = fmaxf(sigma[t], 0.0f);
        if (blockIdx.x == 0) g_s[t] = s;

        float wk = fmaxf(width[t], 0.0f);
        float w0 = fmaxf(wout[(1 + t) * OUTD + o0], 0.0f);
        float w1 = fmaxf(wout[(1 + t) * OUTD + o1], 0.0f);
        float v0 = wk * w0, v1 = wk * w1;
        V0[t] = v0; V1[t] = v1;

        float r0 = v0, r1 = w0, r3 = v1, r4 = w1;
        #pragma unroll
        for (int off = 16; off; off >>= 1) {
            r0 += __shfl_xor_sync(0xffffffffu, r0, off);
            r1 += __shfl_xor_sync(0xffffffffu, r1, off);
            r3 += __shfl_xor_sync(0xffffffffu, r3, off);
            r4 += __shfl_xor_sync(0xffffffffu, r4, off);
        }
        const int warp = t >> 5, lane = t & 31;
        if (lane == 0) {
            red[0 * 8 + warp] = r0; red[1 * 8 + warp] = r1;
            red[3 * 8 + warp] = r3; red[4 * 8 + warp] = r4;
        }
        __syncthreads();   // V0/V1 ready

        float m0a = 0, m0b = 0, m1a = 0, m1b = 0;
        float q0a = 0, q0b = 0, q1a = 0, q1b = 0;
        #pragma unroll 8
        for (int k = 0; k < KK; k += 2) {
            float ca = center[k * DD + t];
            float cb = center[(k + 1) * DD + t];
            float csa = ca * ca, csb = cb * cb;
            m0a = fmaf(ca, V0[k], m0a);      m0b = fmaf(cb, V0[k + 1], m0b);
            m1a = fmaf(ca, V1[k], m1a);      m1b = fmaf(cb, V1[k + 1], m1b);
            q0a = fmaf(csa, V0[k], q0a);     q0b = fmaf(csb, V0[k + 1], q0b);
            q1a = fmaf(csa, V1[k], q1a);     q1b = fmaf(csb, V1[k + 1], q1b);
        }
        write_Bpk(o0, t, 2.0f * s * (m0a + m0b));
        write_Bpk(o1, t, 2.0f * s * (m1a + m1b));

        float q0 = s * (q0a + q0b), q1 = s * (q1a + q1b);
        #pragma unroll
        for (int off = 16; off; off >>= 1) {
            q0 += __shfl_xor_sync(0xffffffffu, q0, off);
            q1 += __shfl_xor_sync(0xffffffffu, q1, off);
        }
        if (lane == 0) { red[2 * 8 + warp] = q0; red[5 * 8 + warp] = q1; }
        __syncthreads();

        if (t < 2) {
            const int o = (t == 0) ? o0 : o1;
            const float* a = red + 3 * t * 8;
            const float* b = red + (3 * t + 1) * 8;
            const float* c = red + (3 * t + 2) * 8;
            float sv = 0, sw = 0, cv = 0;
            #pragma unroll
            for (int w = 0; w < 8; w++) { sv += a[w]; sw += b[w]; cv += c[w]; }
            g_SV[o] = sv;
            g_Bp[o] = fmaxf(wout[o], 0.0f) + sw - cv;
        }

        // release: EVERY thread fences its own global writes, then one signal
        __threadfence();
        __syncthreads();
        if (tid == 0) atomicAdd(&g_ready, 1);
        return;
    }

    // ======================= MAIN: out = Bp - x2*SV + x @ M2' =================
    const int warp = tid >> 5;
    const int lane = tid & 31;
    const int warp_m = warp >> 2;     // 0..1
    const int warp_n = warp & 3;      // 0..3
    const int q8    = lane >> 2;      // 0..7
    const int ql    = lane & 3;       // 0..3

    const int row0 = (blockIdx.x - NPREP) * 64;
    const int sr0  = (tid >> 3) * 2;  // staging rows {sr0, sr0+1}
    const int seg  = tid & 7;         // 4-float segment within 32-col chunk

    const uint32_t abase = (uint32_t)__cvta_generic_to_shared(smU);
    const uint4* Bb = reinterpret_cast<const uint4*>(g_Bpk) + warp_n * 64 + lane;

    const uint32_t sts_b0 = abase + (uint32_t)(sr0 * 128);
    const uint32_t sts_w0 = (uint32_t)((sr0 & 7) << 4);
    const uint32_t sts_w1 = (uint32_t)(((sr0 + 1) & 7) << 4);
    const uint32_t su = (uint32_t)(seg * 8);

    const int rl0 = warp_m * 32 + (lane & 15);
    const uint32_t lds_b0 = abase + (uint32_t)(rl0 * 128);
    const uint32_t lds_w0 = (uint32_t)((rl0 & 7) << 4);
    const uint32_t koff = (uint32_t)((lane >> 4) << 4);

    float acc[2][4][4];
    #pragma unroll
    for (int mt = 0; mt < 2; mt++)
        #pragma unroll
        for (int nt = 0; nt < 4; nt++)
            #pragma unroll
            for (int i = 0; i < 4; i++) acc[mt][nt][i] = 0.0f;

    float x2p0 = 0.0f, x2p1 = 0.0f;

    // issue chunk-0 x loads BEFORE the flag wait (prep-independent; hides prep)
    const float* xptr = x + (size_t)(row0 + sr0) * DD + seg * 4;
    float4 v0 = __ldcs(reinterpret_cast<const float4*>(xptr));
    float4 v1 = __ldcs(reinterpret_cast<const float4*>(xptr + DD));

    // acquire: wait until all prep blocks have published g_Bpk/g_s/g_SV/g_Bp
    if (tid == 0) {
        while (atomicAdd(&g_ready, 0) < NPREP) __nanosleep(100);
        __threadfence();   // acquire ordering for subsequent loads
    }
    __syncthreads();

    #pragma unroll
    for (int c = 0; c < 8; c++) {
        const float4 sv4 = *reinterpret_cast<const float4*>(g_s + c * 32 + seg * 4);
        const uint32_t half64 = (uint32_t)((c & 1) << 6);

        {
            float t0 = v0.x * sv4.x, t1 = v0.y * sv4.y, t2 = v0.z * sv4.z, t3 = v0.w * sv4.w;
            x2p0 += t0 * v0.x + t1 * v0.y + t2 * v0.z + t3 * v0.w;
            uint2 pk = make_uint2(pack_bf16x2(v0.x, v0.y), pack_bf16x2(v0.z, v0.w));
            asm volatile("st.shared.v2.b32 [%0], {%1, %2};"
                :: "r"(sts_b0 + (((half64 | su) ^ sts_w0))), "r"(pk.x), "r"(pk.y) : "memory");
        }
        {
            float t0 = v1.x * sv4.x, t1 = v1.y * sv4.y, t2 = v1.z * sv4.z, t3 = v1.w * sv4.w;
            x2p1 += t0 * v1.x + t1 * v1.y + t2 * v1.z + t3 * v1.w;
            uint2 pk = make_uint2(pack_bf16x2(v1.x, v1.y), pack_bf16x2(v1.z, v1.w));
            asm volatile("st.shared.v2.b32 [%0], {%1, %2};"
                :: "r"(sts_b0 + 128u + (((half64 | su) ^ sts_w1))), "r"(pk.x), "r"(pk.y) : "memory");
        }

        if (c < 7) {
            const float* nb = xptr + (c + 1) * 32;
            v0 = __ldcs(reinterpret_cast<const float4*>(nb));
            v1 = __ldcs(reinterpret_cast<const float4*>(nb + DD));
        }

        __syncthreads();   // A half ready; also orders MMA(c-1) before STS(c+1)

        #pragma unroll
        for (int q = 0; q < 2; q++) {
            const int k16 = c * 2 + q;
            const uint4 bu0 = Bb[k16 * 256];
            const uint4 bu1 = Bb[k16 * 256 + 32];
            const uint32_t u = half64 + (uint32_t)(q * 32) + koff;

            #pragma unroll
            for (int mt = 0; mt < 2; mt++) {
                const uint32_t addr = lds_b0 + (uint32_t)(mt * 16 * 128)
                                    + (u ^ lds_w0);
                uint32_t a0, a1, a2, a3;
                ldsm_x4(a0, a1, a2, a3, addr);
                mma16816(acc[mt][0], a0, a1, a2, a3, bu0.x, bu0.y);
                mma16816(acc[mt][1], a0, a1, a2, a3, bu0.z, bu0.w);
                mma16816(acc[mt][2], a0, a1, a2, a3, bu1.x, bu1.y);
                mma16816(acc[mt][3], a0, a1, a2, a3, bu1.z, bu1.w);
            }
        }
    }

    // ---- finalize x2 ----
    x2p0 += __shfl_xor_sync(0xffffffffu, x2p0, 1);
    x2p0 += __shfl_xor_sync(0xffffffffu, x2p0, 2);
    x2p0 += __shfl_xor_sync(0xffffffffu, x2p0, 4);
    x2p1 += __shfl_xor_sync(0xffffffffu, x2p1, 1);
    x2p1 += __shfl_xor_sync(0xffffffffu, x2p1, 2);
    x2p1 += __shfl_xor_sync(0xffffffffu, x2p1, 4);
    if (seg == 0) {
        x2_sh[sr0] = x2p0;
        x2_sh[sr0 + 1] = x2p1;
    }
    __syncthreads();

    // ---- epilogue: 2 passes x 64 cols; restage -> coalesced STG.128 ----
    float* fb = reinterpret_cast<float*>(smU);   // 64 rows x 68 floats
    const int rr2 = tid >> 4;
    const int f4  = tid & 15;

    #pragma unroll 1
    for (int cc = 0; cc < 2; cc++) {
        if ((warp_n >> 1) == cc) {
            #pragma unroll
            for (int ntl = 0; ntl < 4; ntl++) {
                const int lcol = (warp_n & 1) * 32 + ntl * 8 + 2 * ql;
                #pragma unroll
                for (int mt = 0; mt < 2; mt++) {
                    const int r0 = warp_m * 32 + mt * 16 + q8;
                    *reinterpret_cast<float2*>(fb + r0 * 68 + lcol) =
                        make_float2(acc[mt][ntl][0], acc[mt][ntl][1]);
                    *reinterpret_cast<float2*>(fb + (r0 + 8) * 68 + lcol) =
                        make_float2(acc[mt][ntl][2], acc[mt][ntl][3]);
                }
            }
        }
        __syncthreads();

        const int col0 = cc * 64 + f4 * 4;
        const float4 bp  = *reinterpret_cast<const float4*>(g_Bp + col0);
        const float4 svv = *reinterpret_cast<const float4*>(g_SV + col0);
        #pragma unroll
        for (int i = 0; i < 4; i++) {
            const int row = rr2 + i * 16;
            const float4 u = *reinterpret_cast<const float4*>(fb + row * 68 + f4 * 4);
            const float x2v = x2_sh[row];
            float4 o;
            o.x = u.x + bp.x - x2v * svv.x;
            o.y = u.y + bp.y - x2v * svv.y;
            o.z = u.z + bp.z - x2v * svv.z;
            o.w = u.w + bp.w - x2v * svv.w;
            __stcs(reinterpret_cast<float4*>(out + (size_t)(row0 + row) * OUTD + col0), o);
        }
        __syncthreads();
    }

    // ---- completion: last main block resets handshake for the next replay ----
    if (tid == 0) {
        int old = atomicAdd(&g_done, 1);
        if (old == n_main - 1) {
            g_ready = 0;
            g_done  = 0;
            __threadfence();
        }
    }
}

// ---------------- launcher ----------------
extern "C" void kernel_launch(void* const* d_in, const int* in_sizes, int n_in,
                              void* d_out, int out_size) {
    const float* x      = (const float*)d_in[0];  // [N, D]
    const float* center = (const float*)d_in[1];  // [K, D]
    const float* sigma  = (const float*)d_in[2];  // [D]
    const float* width  = (const float*)d_in[3];  // [K]
    const float* wout   = (const float*)d_in[4];  // [1+K, OUT]
    float* out = (float*)d_out;

    const int N = in_sizes[0] / DD;
    const int n_main = N / 64;

    rbf_fused_kernel<<<NPREP + n_main, 256>>>(x, center, sigma, width, wout,
                                              out, n_main);
}